// round 4
// baseline (speedup 1.0000x reference)
#include <cuda_runtime.h>

// Problem constants
#define BB 32
#define T_IN 1024
#define HH 384
#define T_OUTC 8192
#define KW 11
#define KH (HH*KW)           // 4224
#define TILE_T 32
#define LDSX 385             // padded smem row stride (floats)

// ---------------- scratch (static device globals; no allocations) -----------
__device__ float g_m1[BB*T_IN*HH];    // after conv1+LN+relu
__device__ float g_m2[BB*T_IN*HH];    // after conv2+LN+relu
__device__ float g_wt1[KH*HH];        // conv1 weights transposed to (i*K+k, o)
__device__ float g_wt2[KH*HH];
__device__ float g_cum[BB*T_IN];      // clipped cumsum of durations

// ---------------- weight transpose: w[o][i][k] -> wt[i*K+k][o] --------------
__global__ void wt_kernel(const float* __restrict__ w, float* __restrict__ wt) {
    int j = blockIdx.x * blockDim.x + threadIdx.x;
    if (j >= KH * HH) return;
    int o  = j % HH;
    int ik = j / HH;
    int i  = ik / KW;
    int k  = ik % KW;
    wt[j] = w[o * KH + i * KW + k];
}

// ---------------- fused conv1d(SAME,K=11) + bias + LayerNorm + ReLU ---------
// grid: (T_IN/TILE_T, B), block: 256 threads.
__global__ void __launch_bounds__(256, 2)
conv_ln_relu(const float* __restrict__ in, const float* __restrict__ wt,
             const float* __restrict__ cb, const float* __restrict__ lg,
             const float* __restrict__ lb, float* __restrict__ out) {
    extern __shared__ float xs[];   // (TILE_T+10) x LDSX floats
    const int b   = blockIdx.y;
    const int bt0 = blockIdx.x * TILE_T;
    const int tid = threadIdx.x;

    const float* inb = in + (size_t)b * T_IN * HH;
    for (int e = tid; e < (TILE_T + 10) * (HH / 4); e += 256) {
        int r  = e / (HH / 4);
        int c4 = e % (HH / 4);
        int tg = bt0 + r - 5;
        float4 v = make_float4(0.f, 0.f, 0.f, 0.f);
        if (tg >= 0 && tg < T_IN)
            v = ((const float4*)(inb + (size_t)tg * HH))[c4];
        float* d = &xs[r * LDSX + c4 * 4];
        d[0] = v.x; d[1] = v.y; d[2] = v.z; d[3] = v.w;
    }
    __syncthreads();

    const int ot    = tid & 127;
    const int tbase = (tid >> 7) * 16;

    float a0[16], a1[16], a2[16];
    #pragma unroll
    for (int t = 0; t < 16; t++) { a0[t] = 0.f; a1[t] = 0.f; a2[t] = 0.f; }

    for (int i = 0; i < HH; i++) {
        float xr[26];
        #pragma unroll
        for (int r = 0; r < 26; r++) xr[r] = xs[(tbase + r) * LDSX + i];
        const float* wp = wt + (size_t)i * KW * HH + ot;   // coalesced over ot
        #pragma unroll
        for (int k = 0; k < KW; k++) {
            float w0 = wp[k * HH];
            float w1 = wp[k * HH + 128];
            float w2 = wp[k * HH + 256];
            #pragma unroll
            for (int t = 0; t < 16; t++) {
                float xv = xr[t + k];
                a0[t] += w0 * xv;
                a1[t] += w1 * xv;
                a2[t] += w2 * xv;
            }
        }
    }
    __syncthreads();   // done reading x tile; reuse smem for conv output

    float b0 = cb[ot], b1 = cb[ot + 128], b2 = cb[ot + 256];
    #pragma unroll
    for (int t = 0; t < 16; t++) {
        int tt = tbase + t;
        xs[tt * LDSX + ot]       = a0[t] + b0;
        xs[tt * LDSX + ot + 128] = a1[t] + b1;
        xs[tt * LDSX + ot + 256] = a2[t] + b2;
    }
    __syncthreads();

    // LayerNorm + ReLU, one warp per row (8 warps x 4 rows)
    const int wid  = tid >> 5;
    const int lane = tid & 31;
    for (int rr = 0; rr < 4; rr++) {
        int t = wid * 4 + rr;
        float s1 = 0.f, s2 = 0.f;
        float v[12];
        #pragma unroll
        for (int j = 0; j < 12; j++) {
            float x = xs[t * LDSX + lane + 32 * j];
            v[j] = x; s1 += x; s2 += x * x;
        }
        #pragma unroll
        for (int off = 16; off > 0; off >>= 1) {
            s1 += __shfl_xor_sync(0xffffffffu, s1, off);
            s2 += __shfl_xor_sync(0xffffffffu, s2, off);
        }
        float mu  = s1 * (1.0f / HH);
        float var = s2 * (1.0f / HH) - mu * mu;
        float rs  = rsqrtf(var + 1e-5f);
        float* ob = out + ((size_t)b * T_IN + bt0 + t) * HH;
        #pragma unroll
        for (int j = 0; j < 12; j++) {
            int o = lane + 32 * j;
            float y = (v[j] - mu) * rs * lg[o] + lb[o];
            ob[o] = fmaxf(y, 0.0f);
        }
    }
}

// ---------------- linear head + token mask ----------------------------------
__global__ void lin_mask(const float* __restrict__ m, const float* __restrict__ lw,
                         const float* __restrict__ lbias, const int* __restrict__ tok,
                         float* __restrict__ pred) {
    int row  = blockIdx.x * 4 + (threadIdx.x >> 5);
    int lane = threadIdx.x & 31;
    const float* mr = m + (size_t)row * HH;
    float s = 0.f;
    #pragma unroll
    for (int j = 0; j < 12; j++) {
        int o = lane + 32 * j;
        s += mr[o] * lw[o];
    }
    #pragma unroll
    for (int off = 16; off > 0; off >>= 1)
        s += __shfl_xor_sync(0xffffffffu, s, off);
    if (lane == 0) {
        int b = row >> 10;
        int t = row & 1023;
        float v = s + lbias[0];
        pred[row] = (t < tok[b]) ? v : 0.0f;
    }
}

// ---------------- cumsum matching XLA ReduceWindowRewriter(base=16) ----------
// cum[16b+j] = inner[b][j] + outerscan[b-1]
//   inner[b][j]    = left fold of d[16b .. 16b+j]            (init 0)
//   T_b            = inner[b][15]
//   inner2[c][m]   = left fold of T[16c .. 16c+m]
//   U_c            = inner2[c][15]
//   outerscan[16c+m] = inner2[c][m] + left fold(U_0..U_{c-1})   (c>0)
// All folds strictly sequential -> compiler cannot reassociate; adds only, no FMA.
__global__ void cum_kernel(const float* __restrict__ dur, const int* __restrict__ gt,
                           float* __restrict__ cum) {
    __shared__ float T[64];      // block totals
    __shared__ float U[4];       // super-block totals
    __shared__ float OS[64];     // outer scan of block totals
    const int b = blockIdx.x;
    const int t = threadIdx.x;   // 64 threads
    const float* d = dur + (size_t)b * T_IN + t * 16;

    float p[16];
    float s = 0.0f;
    #pragma unroll 1
    for (int j = 0; j < 16; j++) { s = s + d[j]; p[j] = s; }
    T[t] = s;
    __syncthreads();

    const int c = t >> 4, m = t & 15;
    float s2 = 0.0f;
    #pragma unroll 1
    for (int k = 0; k <= m; k++) s2 = s2 + T[c * 16 + k];
    if (m == 15) U[c] = s2;
    __syncthreads();

    float ex2 = 0.0f;
    #pragma unroll 1
    for (int k = 0; k < c; k++) ex2 = ex2 + U[k];
    float os = (c > 0) ? (s2 + ex2) : s2;
    OS[t] = os;
    __syncthreads();

    const float pre = (t > 0) ? OS[t - 1] : 0.0f;
    const float g   = (float)gt[b];
    float* co = cum + (size_t)b * T_IN + t * 16;
    #pragma unroll
    for (int j = 0; j < 16; j++) {
        float v = (t > 0) ? (p[j] + pre) : p[j];
        co[j] = fminf(v, g);
    }
}

// ---------------- length regulation gather -----------------------------------
__global__ void gather_kernel(const float* __restrict__ x, const float* __restrict__ cum,
                              const int* __restrict__ gt, float* __restrict__ out) {
    int w    = blockIdx.x * 8 + (threadIdx.x >> 5);
    int lane = threadIdx.x & 31;
    int b = w >> 13;          // / T_OUTC
    int f = w & (T_OUTC - 1);
    float4* orow = (float4*)(out + (size_t)w * HH);
    if (f >= gt[b]) {
        float4 z = make_float4(0.f, 0.f, 0.f, 0.f);
        #pragma unroll
        for (int j = 0; j < 3; j++) orow[lane + 32 * j] = z;
        return;
    }
    const float* c = cum + (size_t)b * T_IN;
    float ff = (float)f;
    int lo = 0, hi = T_IN;
    while (lo < hi) {                   // searchsorted side='right'
        int mid = (lo + hi) >> 1;
        if (c[mid] <= ff) lo = mid + 1; else hi = mid;
    }
    int idx = lo < (T_IN - 1) ? lo : (T_IN - 1);
    const float4* xrow = (const float4*)(x + ((size_t)b * T_IN + idx) * HH);
    #pragma unroll
    for (int j = 0; j < 3; j++) orow[lane + 32 * j] = xrow[lane + 32 * j];
}

// ---------------- launch ------------------------------------------------------
extern "C" void kernel_launch(void* const* d_in, const int* in_sizes, int n_in,
                              void* d_out, int out_size) {
    const float* x   = (const float*)d_in[0];
    const int*   tok = (const int*)d_in[1];
    const float* dur = (const float*)d_in[2];
    const int*   gt  = (const int*)d_in[3];
    int base = (in_sizes[4] == HH * HH * KW) ? 4 : 5;
    const float* c1w = (const float*)d_in[base + 0];
    const float* c1b = (const float*)d_in[base + 1];
    const float* l1g = (const float*)d_in[base + 2];
    const float* l1b = (const float*)d_in[base + 3];
    const float* c2w = (const float*)d_in[base + 4];
    const float* c2b = (const float*)d_in[base + 5];
    const float* l2g = (const float*)d_in[base + 6];
    const float* l2b = (const float*)d_in[base + 7];
    const float* lw  = (const float*)d_in[base + 8];
    const float* lbv = (const float*)d_in[base + 9];

    float* out      = (float*)d_out;
    float* pred_out = out + (size_t)BB * T_OUTC * HH;

    float *m1, *m2, *wt1, *wt2, *cum;
    cudaGetSymbolAddress((void**)&m1,  g_m1);
    cudaGetSymbolAddress((void**)&m2,  g_m2);
    cudaGetSymbolAddress((void**)&wt1, g_wt1);
    cudaGetSymbolAddress((void**)&wt2, g_wt2);
    cudaGetSymbolAddress((void**)&cum, g_cum);

    const int smem = (TILE_T + 10) * LDSX * sizeof(float);   // 64,680 B
    cudaFuncSetAttribute(conv_ln_relu, cudaFuncAttributeMaxDynamicSharedMemorySize, smem);

    // weight transposes
    {
        int n = KH * HH;
        int gsz = (n + 255) / 256;
        wt_kernel<<<gsz, 256>>>(c1w, wt1);
        wt_kernel<<<gsz, 256>>>(c2w, wt2);
    }

    // length-regulation path (independent of predictor)
    cum_kernel<<<BB, 64>>>(dur, gt, cum);
    gather_kernel<<<(BB * T_OUTC) / 8, 256>>>(x, cum, gt, out);

    // duration predictor
    dim3 cg(T_IN / TILE_T, BB);
    conv_ln_relu<<<cg, 256, smem>>>(x,  wt1, c1b, l1g, l1b, m1);
    conv_ln_relu<<<cg, 256, smem>>>(m1, wt2, c2b, l2g, l2b, m2);
    lin_mask<<<(BB * T_IN) / 4, 128>>>(m2, lw, lbv, tok, pred_out);
}

// round 5
// speedup vs baseline: 1.2005x; 1.2005x over previous
#include <cuda_runtime.h>

// Problem constants
#define BB 32
#define T_IN 1024
#define HH 384
#define T_OUTC 8192
#define KW 11
#define KH (HH*KW)           // 4224
#define TILE_T 32
#define LDSX 385             // padded smem row stride (floats)

// ---------------- scratch (static device globals; no allocations) -----------
__device__ float g_m1[BB*T_IN*HH];
__device__ float g_m2[BB*T_IN*HH];
__device__ float g_wt1[KH*HH];        // (i*K+k, o) layout
__device__ float g_wt2[KH*HH];
__device__ float g_cum[BB*T_IN];

// ---------------- weight transpose: w[o][i][k] -> wt[i*K+k][o] --------------
__global__ void wt_kernel(const float* __restrict__ w, float* __restrict__ wt) {
    int j = blockIdx.x * blockDim.x + threadIdx.x;
    if (j >= KH * HH) return;
    int o  = j % HH;
    int ik = j / HH;
    int i  = ik / KW;
    int k  = ik % KW;
    wt[j] = w[o * KH + i * KW + k];
}

// ---------------- fused conv1d(SAME,K=11) + bias + LN + ReLU, f32x2 FMA -----
// grid: (T_IN/TILE_T, B), block 256.
// Thread map: op = tid&63 owns o-pairs {2op,2op+1}, {2op+128,2op+129},
//             {2op+256,2op+257}; tg = tid>>6 owns t in [tg*8, tg*8+8).
__global__ void __launch_bounds__(256, 2)
conv_ln_relu(const float* __restrict__ in, const float* __restrict__ wt,
             const float* __restrict__ cb, const float* __restrict__ lg,
             const float* __restrict__ lb, float* __restrict__ out) {
    extern __shared__ float xs[];   // (TILE_T+10) x LDSX floats
    const int b   = blockIdx.y;
    const int bt0 = blockIdx.x * TILE_T;
    const int tid = threadIdx.x;

    // Load input tile rows [bt0-5, bt0+TILE_T+5) with zero padding, float4.
    const float* inb = in + (size_t)b * T_IN * HH;
    for (int e = tid; e < (TILE_T + 10) * (HH / 4); e += 256) {
        int r  = e / (HH / 4);
        int c4 = e % (HH / 4);
        int tg = bt0 + r - 5;
        float4 v = make_float4(0.f, 0.f, 0.f, 0.f);
        if (tg >= 0 && tg < T_IN)
            v = ((const float4*)(inb + (size_t)tg * HH))[c4];
        float* d = &xs[r * LDSX + c4 * 4];
        d[0] = v.x; d[1] = v.y; d[2] = v.z; d[3] = v.w;
    }
    __syncthreads();

    const int op    = tid & 63;
    const int tbase = (tid >> 6) * 8;

    // f32x2 accumulators: lane0 = channel 2op+off, lane1 = channel 2op+1+off
    unsigned long long acc0[8], acc1[8], acc2[8];
    #pragma unroll
    for (int t = 0; t < 8; t++) { acc0[t] = 0ULL; acc1[t] = 0ULL; acc2[t] = 0ULL; }

    for (int i = 0; i < HH; i++) {
        // broadcast-packed x values xb[r] = (x, x) for rows tbase..tbase+17
        unsigned long long xb[18];
        #pragma unroll
        for (int r = 0; r < 18; r++) {
            float xv = xs[(tbase + r) * LDSX + i];   // warp-broadcast LDS
            asm("mov.b64 %0, {%1, %1};" : "=l"(xb[r]) : "f"(xv));
        }
        const float2* wp = (const float2*)(wt + (size_t)i * KW * HH) + op;
        #pragma unroll
        for (int k = 0; k < KW; k++) {
            float2 w0 = wp[k * 192];
            float2 w1 = wp[k * 192 + 64];
            float2 w2 = wp[k * 192 + 128];
            unsigned long long W0, W1, W2;
            asm("mov.b64 %0, {%1, %2};" : "=l"(W0) : "f"(w0.x), "f"(w0.y));
            asm("mov.b64 %0, {%1, %2};" : "=l"(W1) : "f"(w1.x), "f"(w1.y));
            asm("mov.b64 %0, {%1, %2};" : "=l"(W2) : "f"(w2.x), "f"(w2.y));
            #pragma unroll
            for (int tp = 0; tp < 8; tp++) {
                unsigned long long xv = xb[tp + k];
                asm("fma.rn.f32x2 %0, %1, %2, %0;" : "+l"(acc0[tp]) : "l"(xv), "l"(W0));
                asm("fma.rn.f32x2 %0, %1, %2, %0;" : "+l"(acc1[tp]) : "l"(xv), "l"(W1));
                asm("fma.rn.f32x2 %0, %1, %2, %0;" : "+l"(acc2[tp]) : "l"(xv), "l"(W2));
            }
        }
    }
    __syncthreads();   // done reading x tile; reuse smem for conv output

    // unpack + bias -> smem [t][o]
    {
        const int o0 = 2 * op;
        float bx0 = cb[o0],       by0 = cb[o0 + 1];
        float bx1 = cb[o0 + 128], by1 = cb[o0 + 129];
        float bx2 = cb[o0 + 256], by2 = cb[o0 + 257];
        #pragma unroll
        for (int tp = 0; tp < 8; tp++) {
            int tt = tbase + tp;
            float lo, hi;
            asm("mov.b64 {%0, %1}, %2;" : "=f"(lo), "=f"(hi) : "l"(acc0[tp]));
            xs[tt * LDSX + o0]       = lo + bx0;
            xs[tt * LDSX + o0 + 1]   = hi + by0;
            asm("mov.b64 {%0, %1}, %2;" : "=f"(lo), "=f"(hi) : "l"(acc1[tp]));
            xs[tt * LDSX + o0 + 128] = lo + bx1;
            xs[tt * LDSX + o0 + 129] = hi + by1;
            asm("mov.b64 {%0, %1}, %2;" : "=f"(lo), "=f"(hi) : "l"(acc2[tp]));
            xs[tt * LDSX + o0 + 256] = lo + bx2;
            xs[tt * LDSX + o0 + 257] = hi + by2;
        }
    }
    __syncthreads();

    // LayerNorm + ReLU, one warp per row (8 warps x 4 rows)
    const int wid  = tid >> 5;
    const int lane = tid & 31;
    for (int rr = 0; rr < 4; rr++) {
        int t = wid * 4 + rr;
        float s1 = 0.f, s2 = 0.f;
        float v[12];
        #pragma unroll
        for (int j = 0; j < 12; j++) {
            float x = xs[t * LDSX + lane + 32 * j];
            v[j] = x; s1 += x; s2 += x * x;
        }
        #pragma unroll
        for (int off = 16; off > 0; off >>= 1) {
            s1 += __shfl_xor_sync(0xffffffffu, s1, off);
            s2 += __shfl_xor_sync(0xffffffffu, s2, off);
        }
        float mu  = s1 * (1.0f / HH);
        float var = s2 * (1.0f / HH) - mu * mu;
        float rs  = rsqrtf(var + 1e-5f);
        float* ob = out + ((size_t)b * T_IN + bt0 + t) * HH;
        #pragma unroll
        for (int j = 0; j < 12; j++) {
            int o = lane + 32 * j;
            float y = (v[j] - mu) * rs * lg[o] + lb[o];
            ob[o] = fmaxf(y, 0.0f);
        }
    }
}

// ---------------- linear head + token mask ----------------------------------
__global__ void lin_mask(const float* __restrict__ m, const float* __restrict__ lw,
                         const float* __restrict__ lbias, const int* __restrict__ tok,
                         float* __restrict__ pred) {
    int row  = blockIdx.x * 4 + (threadIdx.x >> 5);
    int lane = threadIdx.x & 31;
    const float* mr = m + (size_t)row * HH;
    float s = 0.f;
    #pragma unroll
    for (int j = 0; j < 12; j++) {
        int o = lane + 32 * j;
        s += mr[o] * lw[o];
    }
    #pragma unroll
    for (int off = 16; off > 0; off >>= 1)
        s += __shfl_xor_sync(0xffffffffu, s, off);
    if (lane == 0) {
        int b = row >> 10;
        int t = row & 1023;
        float v = s + lbias[0];
        pred[row] = (t < tok[b]) ? v : 0.0f;
    }
}

// ---------------- cumsum matching XLA ReduceWindowRewriter(base=16) ----------
__global__ void cum_kernel(const float* __restrict__ dur, const int* __restrict__ gt,
                           float* __restrict__ cum) {
    __shared__ float T[64];
    __shared__ float U[4];
    __shared__ float OS[64];
    const int b = blockIdx.x;
    const int t = threadIdx.x;   // 64 threads
    const float* d = dur + (size_t)b * T_IN + t * 16;

    float p[16];
    float s = 0.0f;
    #pragma unroll 1
    for (int j = 0; j < 16; j++) { s = s + d[j]; p[j] = s; }
    T[t] = s;
    __syncthreads();

    const int c = t >> 4, m = t & 15;
    float s2 = 0.0f;
    #pragma unroll 1
    for (int k = 0; k <= m; k++) s2 = s2 + T[c * 16 + k];
    if (m == 15) U[c] = s2;
    __syncthreads();

    float ex2 = 0.0f;
    #pragma unroll 1
    for (int k = 0; k < c; k++) ex2 = ex2 + U[k];
    float os = (c > 0) ? (s2 + ex2) : s2;
    OS[t] = os;
    __syncthreads();

    const float pre = (t > 0) ? OS[t - 1] : 0.0f;
    const float g   = (float)gt[b];
    float* co = cum + (size_t)b * T_IN + t * 16;
    #pragma unroll
    for (int j = 0; j < 16; j++) {
        float v = (t > 0) ? (p[j] + pre) : p[j];
        co[j] = fminf(v, g);
    }
}

// ---------------- length regulation gather -----------------------------------
__global__ void gather_kernel(const float* __restrict__ x, const float* __restrict__ cum,
                              const int* __restrict__ gt, float* __restrict__ out) {
    int w    = blockIdx.x * 8 + (threadIdx.x >> 5);
    int lane = threadIdx.x & 31;
    int b = w >> 13;
    int f = w & (T_OUTC - 1);
    float4* orow = (float4*)(out + (size_t)w * HH);
    if (f >= gt[b]) {
        float4 z = make_float4(0.f, 0.f, 0.f, 0.f);
        #pragma unroll
        for (int j = 0; j < 3; j++) orow[lane + 32 * j] = z;
        return;
    }
    const float* c = cum + (size_t)b * T_IN;
    float ff = (float)f;
    int lo = 0, hi = T_IN;
    while (lo < hi) {
        int mid = (lo + hi) >> 1;
        if (c[mid] <= ff) lo = mid + 1; else hi = mid;
    }
    int idx = lo < (T_IN - 1) ? lo : (T_IN - 1);
    const float4* xrow = (const float4*)(x + ((size_t)b * T_IN + idx) * HH);
    #pragma unroll
    for (int j = 0; j < 3; j++) orow[lane + 32 * j] = xrow[lane + 32 * j];
}

// ---------------- launch ------------------------------------------------------
extern "C" void kernel_launch(void* const* d_in, const int* in_sizes, int n_in,
                              void* d_out, int out_size) {
    const float* x   = (const float*)d_in[0];
    const int*   tok = (const int*)d_in[1];
    const float* dur = (const float*)d_in[2];
    const int*   gt  = (const int*)d_in[3];
    int base = (in_sizes[4] == HH * HH * KW) ? 4 : 5;
    const float* c1w = (const float*)d_in[base + 0];
    const float* c1b = (const float*)d_in[base + 1];
    const float* l1g = (const float*)d_in[base + 2];
    const float* l1b = (const float*)d_in[base + 3];
    const float* c2w = (const float*)d_in[base + 4];
    const float* c2b = (const float*)d_in[base + 5];
    const float* l2g = (const float*)d_in[base + 6];
    const float* l2b = (const float*)d_in[base + 7];
    const float* lw  = (const float*)d_in[base + 8];
    const float* lbv = (const float*)d_in[base + 9];

    float* out      = (float*)d_out;
    float* pred_out = out + (size_t)BB * T_OUTC * HH;

    float *m1, *m2, *wt1, *wt2, *cum;
    cudaGetSymbolAddress((void**)&m1,  g_m1);
    cudaGetSymbolAddress((void**)&m2,  g_m2);
    cudaGetSymbolAddress((void**)&wt1, g_wt1);
    cudaGetSymbolAddress((void**)&wt2, g_wt2);
    cudaGetSymbolAddress((void**)&cum, g_cum);

    const int smem = (TILE_T + 10) * LDSX * sizeof(float);   // 64,680 B
    cudaFuncSetAttribute(conv_ln_relu, cudaFuncAttributeMaxDynamicSharedMemorySize, smem);

    // weight transposes
    {
        int n = KH * HH;
        int gsz = (n + 255) / 256;
        wt_kernel<<<gsz, 256>>>(c1w, wt1);
        wt_kernel<<<gsz, 256>>>(c2w, wt2);
    }

    // length-regulation path (independent of predictor)
    cum_kernel<<<BB, 64>>>(dur, gt, cum);
    gather_kernel<<<(BB * T_OUTC) / 8, 256>>>(x, cum, gt, out);

    // duration predictor
    dim3 cg(T_IN / TILE_T, BB);
    conv_ln_relu<<<cg, 256, smem>>>(x,  wt1, c1b, l1g, l1b, m1);
    conv_ln_relu<<<cg, 256, smem>>>(m1, wt2, c2b, l2g, l2b, m2);
    lin_mask<<<(BB * T_IN) / 4, 128>>>(m2, lw, lbv, tok, pred_out);
}